// round 1
// baseline (speedup 1.0000x reference)
#include <cuda_runtime.h>

#define N_USER 50000
#define N_ITEM 20000
#define D_IN   128
#define D_HID  256
#define D_OUT  128
#define NE     300000
#define NL     200000

// ---------------- device scratch (static, allocation-free) ----------------
__device__ float g_deg_user[N_USER];
__device__ float g_deg_item[N_ITEM];
__device__ float g_agg1_item[N_ITEM * D_IN];
__device__ float g_agg1_user[N_USER * D_IN];
__device__ float g_h_item[N_ITEM * D_HID];
__device__ float g_h_user[N_USER * D_HID];
__device__ float g_agg2_item[N_ITEM * D_HID];
__device__ float g_agg2_user[N_USER * D_HID];
__device__ float g_z_item[N_ITEM * D_OUT];
__device__ float g_z_user[N_USER * D_OUT];

// ---------------- zero fill ----------------
__global__ void zero_kernel(float4* __restrict__ p, int n4) {
    int i = blockIdx.x * blockDim.x + threadIdx.x;
    if (i < n4) p[i] = make_float4(0.f, 0.f, 0.f, 0.f);
}

// ---------------- layer-1 edge scatter (128-dim) + degree count ----------------
// one warp per edge; lane handles one float4 (4 dims) of the 128-dim row
__global__ void scatter_l1(const float* __restrict__ x_user,
                           const float* __restrict__ x_item,
                           const int* __restrict__ src,
                           const int* __restrict__ dst) {
    int gt = blockIdx.x * blockDim.x + threadIdx.x;
    int e = gt >> 5;
    int lane = gt & 31;
    if (e >= NE) return;
    int s = src[e];
    int d = dst[e];

    float4 vu = ((const float4*)x_user)[s * 32 + lane];
    float* pi = g_agg1_item + d * 128 + lane * 4;
    atomicAdd(pi + 0, vu.x);
    atomicAdd(pi + 1, vu.y);
    atomicAdd(pi + 2, vu.z);
    atomicAdd(pi + 3, vu.w);

    float4 vi = ((const float4*)x_item)[d * 32 + lane];
    float* pu = g_agg1_user + s * 128 + lane * 4;
    atomicAdd(pu + 0, vi.x);
    atomicAdd(pu + 1, vi.y);
    atomicAdd(pu + 2, vi.z);
    atomicAdd(pu + 3, vi.w);

    if (lane == 0) {
        atomicAdd(&g_deg_item[d], 1.f);
        atomicAdd(&g_deg_user[s], 1.f);
    }
}

// ---------------- invert degrees (in place: deg -> 1/max(deg,1)) ----------------
__global__ void invdeg_kernel() {
    int i = blockIdx.x * blockDim.x + threadIdx.x;
    if (i < N_USER) g_deg_user[i] = 1.f / fmaxf(g_deg_user[i], 1.f);
    if (i < N_ITEM) g_deg_item[i] = 1.f / fmaxf(g_deg_item[i], 1.f);
}

// ---------------- layer-2 edge scatter (256-dim) ----------------
__global__ void scatter_l2(const int* __restrict__ src,
                           const int* __restrict__ dst) {
    int gt = blockIdx.x * blockDim.x + threadIdx.x;
    int e = gt >> 5;
    int lane = gt & 31;
    if (e >= NE) return;
    int s = src[e];
    int d = dst[e];

#pragma unroll
    for (int r = 0; r < 2; r++) {
        float4 hu = ((const float4*)g_h_user)[s * 64 + lane * 2 + r];
        float* pi = g_agg2_item + d * 256 + lane * 8 + r * 4;
        atomicAdd(pi + 0, hu.x);
        atomicAdd(pi + 1, hu.y);
        atomicAdd(pi + 2, hu.z);
        atomicAdd(pi + 3, hu.w);

        float4 hi = ((const float4*)g_h_item)[d * 64 + lane * 2 + r];
        float* pu = g_agg2_user + s * 256 + lane * 8 + r * 4;
        atomicAdd(pu + 0, hi.x);
        atomicAdd(pu + 1, hi.y);
        atomicAdd(pu + 2, hi.z);
        atomicAdd(pu + 3, hi.w);
    }
}

// ---------------- fused SAGE GEMM: C = (A1 * invdeg) @ W1 + A2 @ W2 + bias [, relu] ----------------
// A1, A2: [M, K] row-major. W1, W2: [K, N] row-major. bias: [N]. C: [M, N].
// BM=BN=64, BK=16, 256 threads, 4x4 per-thread microtile.
template <int K, int N>
__global__ __launch_bounds__(256)
void gemm_fused(int M,
                const float* __restrict__ A1, const float* __restrict__ invdeg,
                const float* __restrict__ A2,
                const float* __restrict__ W1, const float* __restrict__ W2,
                const float* __restrict__ bias, float* __restrict__ C, int relu) {
    __shared__ float As[16][64];
    __shared__ float Bs[16][64];

    int tid = threadIdx.x;
    int tx = tid & 15;        // 0..15 -> N microtile
    int ty = tid >> 4;        // 0..15 -> M microtile
    int bm = blockIdx.y;
    int bn = blockIdx.x;

    int arow = tid >> 2;              // 0..63
    int acol = (tid & 3) * 4;         // 0,4,8,12
    int brow = tid >> 4;              // 0..15
    int bcol = (tid & 15) * 4;        // 0..60

    int m_a = bm * 64 + arow;

    float acc[4][4];
#pragma unroll
    for (int i = 0; i < 4; i++)
#pragma unroll
        for (int j = 0; j < 4; j++) acc[i][j] = 0.f;

    const int NT = (2 * K) / 16;
    for (int kt = 0; kt < NT; kt++) {
        bool ph1 = (kt < K / 16);
        const float* Ap = ph1 ? A1 : A2;
        const float* Wp = ph1 ? W1 : W2;
        int k0 = ph1 ? kt * 16 : kt * 16 - K;

        float4 av = make_float4(0.f, 0.f, 0.f, 0.f);
        if (m_a < M) {
            av = *(const float4*)(Ap + (size_t)m_a * K + k0 + acol);
            if (ph1) {
                float sc = invdeg[m_a];
                av.x *= sc; av.y *= sc; av.z *= sc; av.w *= sc;
            }
        }
        float4 bv = *(const float4*)(Wp + (size_t)(k0 + brow) * N + bn * 64 + bcol);

        __syncthreads();
        As[acol + 0][arow] = av.x;
        As[acol + 1][arow] = av.y;
        As[acol + 2][arow] = av.z;
        As[acol + 3][arow] = av.w;
        *(float4*)&Bs[brow][bcol] = bv;
        __syncthreads();

#pragma unroll
        for (int k = 0; k < 16; k++) {
            float4 a4 = *(float4*)&As[k][ty * 4];
            float4 b4 = *(float4*)&Bs[k][tx * 4];
            float aa[4] = {a4.x, a4.y, a4.z, a4.w};
            float bb[4] = {b4.x, b4.y, b4.z, b4.w};
#pragma unroll
            for (int i = 0; i < 4; i++)
#pragma unroll
                for (int j = 0; j < 4; j++) acc[i][j] += aa[i] * bb[j];
        }
    }

    float4 bz = *(const float4*)(bias + bn * 64 + tx * 4);
    float bb[4] = {bz.x, bz.y, bz.z, bz.w};
#pragma unroll
    for (int i = 0; i < 4; i++) {
        int m = bm * 64 + ty * 4 + i;
        if (m < M) {
            float4 o;
            o.x = acc[i][0] + bb[0];
            o.y = acc[i][1] + bb[1];
            o.z = acc[i][2] + bb[2];
            o.w = acc[i][3] + bb[3];
            if (relu) {
                o.x = fmaxf(o.x, 0.f);
                o.y = fmaxf(o.y, 0.f);
                o.z = fmaxf(o.z, 0.f);
                o.w = fmaxf(o.w, 0.f);
            }
            *(float4*)(C + (size_t)m * N + bn * 64 + tx * 4) = o;
        }
    }
}

// ---------------- decode: out[i] = -dot(z_user[ls], z_item[ld]); out[L+i] = +dot ----------------
__global__ void decode_kernel(const int* __restrict__ ls,
                              const int* __restrict__ ld,
                              float* __restrict__ out) {
    int gt = blockIdx.x * blockDim.x + threadIdx.x;
    int i = gt >> 5;
    int lane = gt & 31;
    if (i >= NL) return;
    int a = ls[i];
    int b = ld[i];
    float4 u = ((const float4*)g_z_user)[a * 32 + lane];
    float4 v = ((const float4*)g_z_item)[b * 32 + lane];
    float s = u.x * v.x + u.y * v.y + u.z * v.z + u.w * v.w;
#pragma unroll
    for (int o = 16; o > 0; o >>= 1) s += __shfl_down_sync(0xffffffffu, s, o);
    if (lane == 0) {
        out[i] = -s;
        out[NL + i] = s;
    }
}

// ---------------- host launch ----------------
static inline void zero_buf(float* p, int n) {
    int n4 = n / 4;
    zero_kernel<<<(n4 + 255) / 256, 256>>>((float4*)p, n4);
}

extern "C" void kernel_launch(void* const* d_in, const int* in_sizes, int n_in,
                              void* d_out, int out_size) {
    const float* x_user = (const float*)d_in[0];
    const float* x_item = (const float*)d_in[1];
    const float* Wl1_ui = (const float*)d_in[2];
    const float* Wr1_ui = (const float*)d_in[3];
    const float* b1_ui  = (const float*)d_in[4];
    const float* Wl1_iu = (const float*)d_in[5];
    const float* Wr1_iu = (const float*)d_in[6];
    const float* b1_iu  = (const float*)d_in[7];
    const float* Wl2_ui = (const float*)d_in[8];
    const float* Wr2_ui = (const float*)d_in[9];
    const float* b2_ui  = (const float*)d_in[10];
    const float* Wl2_iu = (const float*)d_in[11];
    const float* Wr2_iu = (const float*)d_in[12];
    const float* b2_iu  = (const float*)d_in[13];
    const int* src_u     = (const int*)d_in[14];
    const int* dst_i     = (const int*)d_in[15];
    const int* label_src = (const int*)d_in[16];
    const int* label_dst = (const int*)d_in[17];

    float *deg_u, *deg_i, *a1i, *a1u, *hi, *hu, *a2i, *a2u, *zi, *zu;
    cudaGetSymbolAddress((void**)&deg_u, g_deg_user);
    cudaGetSymbolAddress((void**)&deg_i, g_deg_item);
    cudaGetSymbolAddress((void**)&a1i, g_agg1_item);
    cudaGetSymbolAddress((void**)&a1u, g_agg1_user);
    cudaGetSymbolAddress((void**)&hi, g_h_item);
    cudaGetSymbolAddress((void**)&hu, g_h_user);
    cudaGetSymbolAddress((void**)&a2i, g_agg2_item);
    cudaGetSymbolAddress((void**)&a2u, g_agg2_user);
    cudaGetSymbolAddress((void**)&zi, g_z_item);
    cudaGetSymbolAddress((void**)&zu, g_z_user);

    // zero accumulators + degree counters
    zero_buf(a1i, N_ITEM * D_IN);
    zero_buf(a1u, N_USER * D_IN);
    zero_buf(a2i, N_ITEM * D_HID);
    zero_buf(a2u, N_USER * D_HID);
    zero_buf(deg_u, N_USER);
    zero_buf(deg_i, N_ITEM);

    // layer 1: scatter + degrees
    {
        long long threads = (long long)NE * 32;
        scatter_l1<<<(int)((threads + 255) / 256), 256>>>(x_user, x_item, src_u, dst_i);
    }
    invdeg_kernel<<<(N_USER + 255) / 256, 256>>>();

    // layer 1 GEMMs (K=128 each branch, N=256), relu
    gemm_fused<128, 256><<<dim3(4, (N_ITEM + 63) / 64), 256>>>(
        N_ITEM, a1i, deg_i, x_item, Wl1_ui, Wr1_ui, b1_ui, hi, 1);
    gemm_fused<128, 256><<<dim3(4, (N_USER + 63) / 64), 256>>>(
        N_USER, a1u, deg_u, x_user, Wl1_iu, Wr1_iu, b1_iu, hu, 1);

    // layer 2: scatter 256-dim hidden features
    {
        long long threads = (long long)NE * 32;
        scatter_l2<<<(int)((threads + 255) / 256), 256>>>(src_u, dst_i);
    }

    // layer 2 GEMMs (K=256 each branch, N=128), no relu
    gemm_fused<256, 128><<<dim3(2, (N_ITEM + 63) / 64), 256>>>(
        N_ITEM, a2i, deg_i, hi, Wl2_ui, Wr2_ui, b2_ui, zi, 0);
    gemm_fused<256, 128><<<dim3(2, (N_USER + 63) / 64), 256>>>(
        N_USER, a2u, deg_u, hu, Wl2_iu, Wr2_iu, b2_iu, zu, 0);

    // decode
    {
        long long threads = (long long)NL * 32;
        decode_kernel<<<(int)((threads + 255) / 256), 256>>>(label_src, label_dst, (float*)d_out);
    }
}

// round 2
// speedup vs baseline: 1.5151x; 1.5151x over previous
#include <cuda_runtime.h>

#define N_USER 50000
#define N_ITEM 20000
#define D_IN   128
#define D_HID  256
#define D_OUT  128
#define NE     300000
#define NL     200000

// ---------------- device scratch (static, allocation-free) ----------------
__device__ float g_deg_user[N_USER];
__device__ float g_deg_item[N_ITEM];
__device__ float g_agg1_item[N_ITEM * D_IN];
__device__ float g_agg1_user[N_USER * D_IN];
__device__ float g_h_item[N_ITEM * D_HID];
__device__ float g_h_user[N_USER * D_HID];
__device__ float g_agg2_item[N_ITEM * D_HID];
__device__ float g_agg2_user[N_USER * D_HID];
__device__ float g_z_item[N_ITEM * D_OUT];
__device__ float g_z_user[N_USER * D_OUT];

// ---------------- fused zero fill (up to 4 buffers in one launch) ----------------
__global__ void zero_multi(float4* p0, int n0, float4* p1, int n1,
                           float4* p2, int n2, float4* p3, int n3) {
    int i = blockIdx.x * blockDim.x + threadIdx.x;
    float4 z = make_float4(0.f, 0.f, 0.f, 0.f);
    if (i < n0) p0[i] = z;
    if (i < n1) p1[i] = z;
    if (i < n2) p2[i] = z;
    if (i < n3) p3[i] = z;
}

// ---------------- vectorized global reduction (sm_90+: red.global.add.v4.f32) ----
__device__ __forceinline__ void red_add_v4(float* p, float4 v) {
    asm volatile("red.global.add.v4.f32 [%0], {%1, %2, %3, %4};"
                 :: "l"(p), "f"(v.x), "f"(v.y), "f"(v.z), "f"(v.w)
                 : "memory");
}

// ---------------- layer-1 edge scatter (128-dim) + degree count ----------------
// one warp per edge; lane handles one float4 (4 dims) of the 128-dim row
__global__ void scatter_l1(const float* __restrict__ x_user,
                           const float* __restrict__ x_item,
                           const int* __restrict__ src,
                           const int* __restrict__ dst) {
    int gt = blockIdx.x * blockDim.x + threadIdx.x;
    int e = gt >> 5;
    int lane = gt & 31;
    if (e >= NE) return;
    int s = __ldg(src + e);
    int d = __ldg(dst + e);

    float4 vu = __ldg(&((const float4*)x_user)[s * 32 + lane]);
    red_add_v4(g_agg1_item + d * 128 + lane * 4, vu);

    float4 vi = __ldg(&((const float4*)x_item)[d * 32 + lane]);
    red_add_v4(g_agg1_user + s * 128 + lane * 4, vi);

    if (lane == 0) {
        atomicAdd(&g_deg_item[d], 1.f);
        atomicAdd(&g_deg_user[s], 1.f);
    }
}

// ---------------- invert degrees (in place: deg -> 1/max(deg,1)) ----------------
__global__ void invdeg_kernel() {
    int i = blockIdx.x * blockDim.x + threadIdx.x;
    if (i < N_USER) g_deg_user[i] = 1.f / fmaxf(g_deg_user[i], 1.f);
    if (i < N_ITEM) g_deg_item[i] = 1.f / fmaxf(g_deg_item[i], 1.f);
}

// ---------------- layer-2 edge scatter (256-dim) ----------------
__global__ void scatter_l2(const int* __restrict__ src,
                           const int* __restrict__ dst) {
    int gt = blockIdx.x * blockDim.x + threadIdx.x;
    int e = gt >> 5;
    int lane = gt & 31;
    if (e >= NE) return;
    int s = __ldg(src + e);
    int d = __ldg(dst + e);

#pragma unroll
    for (int r = 0; r < 2; r++) {
        float4 hu = ((const float4*)g_h_user)[s * 64 + lane * 2 + r];
        red_add_v4(g_agg2_item + d * 256 + lane * 8 + r * 4, hu);

        float4 hi = ((const float4*)g_h_item)[d * 64 + lane * 2 + r];
        red_add_v4(g_agg2_user + s * 256 + lane * 8 + r * 4, hi);
    }
}

// ---------------- fused SAGE GEMM ----------------
// C = (A1 * invdeg) @ W1 + A2 @ W2 + bias [, relu]
// A1, A2: [M, K] row-major. W1, W2: [K, N] row-major. bias: [N]. C: [M, N].
// BM=BN=128, BK=16, 256 threads, 8x8 per-thread microtile, double-buffered smem.
template <int K, int N>
__device__ __forceinline__ void load_tile(
    int kt, int M, int m0, int m1, int acol, int brow, int bcol, int bn,
    const float* __restrict__ A1, const float* __restrict__ A2,
    const float* __restrict__ W1, const float* __restrict__ W2,
    float invd0, float invd1,
    float4& a0, float4& a1v, float4& b0, float4& b1)
{
    bool ph1 = kt < K / 16;
    const float* Ap = ph1 ? A1 : A2;
    const float* Wp = ph1 ? W1 : W2;
    int k0 = ph1 ? kt * 16 : kt * 16 - K;

    a0 = make_float4(0.f, 0.f, 0.f, 0.f);
    a1v = a0;
    if (m0 < M) a0 = *(const float4*)(Ap + (size_t)m0 * K + k0 + acol);
    if (m1 < M) a1v = *(const float4*)(Ap + (size_t)m1 * K + k0 + acol);
    if (ph1) {
        a0.x *= invd0; a0.y *= invd0; a0.z *= invd0; a0.w *= invd0;
        a1v.x *= invd1; a1v.y *= invd1; a1v.z *= invd1; a1v.w *= invd1;
    }
    const float* wb = Wp + (size_t)k0 * N + (size_t)bn * 128 + bcol;
    b0 = *(const float4*)(wb + (size_t)brow * N);
    b1 = *(const float4*)(wb + (size_t)(brow + 8) * N);
}

template <int K, int N>
__global__ __launch_bounds__(256)
void gemm_fused(int M,
                const float* __restrict__ A1, const float* __restrict__ invdeg,
                const float* __restrict__ A2,
                const float* __restrict__ W1, const float* __restrict__ W2,
                const float* __restrict__ bias, float* __restrict__ C, int relu) {
    __shared__ float As[2][16][132];  // +4 pad: kills STS bank conflicts, keeps 16B align
    __shared__ float Bs[2][16][128];

    const int tid = threadIdx.x;
    const int tx = tid & 15;        // N microtile (8 cols)
    const int ty = tid >> 4;        // M microtile (8 rows)
    const int bm = blockIdx.y;
    const int bn = blockIdx.x;

    const int arow = tid >> 2;              // 0..63
    const int acol = (tid & 3) << 2;        // 0,4,8,12
    const int brow = tid >> 5;              // 0..7
    const int bcol = (tid & 31) << 2;       // 0..124

    const int m0 = bm * 128 + arow;
    const int m1 = m0 + 64;

    float invd0 = (m0 < M) ? invdeg[m0] : 1.f;
    float invd1 = (m1 < M) ? invdeg[m1] : 1.f;

    float acc[8][8];
#pragma unroll
    for (int i = 0; i < 8; i++)
#pragma unroll
        for (int j = 0; j < 8; j++) acc[i][j] = 0.f;

    const int NT = (2 * K) / 16;

    float4 ra0, ra1, rb0, rb1;
    load_tile<K, N>(0, M, m0, m1, acol, brow, bcol, bn, A1, A2, W1, W2,
                    invd0, invd1, ra0, ra1, rb0, rb1);
    int buf = 0;
    {
        As[buf][acol + 0][arow] = ra0.x;
        As[buf][acol + 1][arow] = ra0.y;
        As[buf][acol + 2][arow] = ra0.z;
        As[buf][acol + 3][arow] = ra0.w;
        As[buf][acol + 0][arow + 64] = ra1.x;
        As[buf][acol + 1][arow + 64] = ra1.y;
        As[buf][acol + 2][arow + 64] = ra1.z;
        As[buf][acol + 3][arow + 64] = ra1.w;
        *(float4*)&Bs[buf][brow][bcol] = rb0;
        *(float4*)&Bs[buf][brow + 8][bcol] = rb1;
    }
    __syncthreads();

    for (int kt = 0; kt < NT; kt++) {
        bool more = (kt + 1) < NT;
        float4 na0, na1, nb0, nb1;
        if (more)
            load_tile<K, N>(kt + 1, M, m0, m1, acol, brow, bcol, bn, A1, A2, W1, W2,
                            invd0, invd1, na0, na1, nb0, nb1);

#pragma unroll
        for (int k = 0; k < 16; k++) {
            float4 aA = *(float4*)&As[buf][k][ty * 8];
            float4 aB = *(float4*)&As[buf][k][ty * 8 + 4];
            float4 bA = *(float4*)&Bs[buf][k][tx * 8];
            float4 bB = *(float4*)&Bs[buf][k][tx * 8 + 4];
            float a8[8] = {aA.x, aA.y, aA.z, aA.w, aB.x, aB.y, aB.z, aB.w};
            float b8[8] = {bA.x, bA.y, bA.z, bA.w, bB.x, bB.y, bB.z, bB.w};
#pragma unroll
            for (int i = 0; i < 8; i++)
#pragma unroll
                for (int j = 0; j < 8; j++) acc[i][j] += a8[i] * b8[j];
        }

        if (more) {
            buf ^= 1;
            As[buf][acol + 0][arow] = na0.x;
            As[buf][acol + 1][arow] = na0.y;
            As[buf][acol + 2][arow] = na0.z;
            As[buf][acol + 3][arow] = na0.w;
            As[buf][acol + 0][arow + 64] = na1.x;
            As[buf][acol + 1][arow + 64] = na1.y;
            As[buf][acol + 2][arow + 64] = na1.z;
            As[buf][acol + 3][arow + 64] = na1.w;
            *(float4*)&Bs[buf][brow][bcol] = nb0;
            *(float4*)&Bs[buf][brow + 8][bcol] = nb1;
            __syncthreads();
        }
    }

    // epilogue
    float bb[8];
    {
        float4 z0 = *(const float4*)(bias + bn * 128 + tx * 8);
        float4 z1 = *(const float4*)(bias + bn * 128 + tx * 8 + 4);
        bb[0] = z0.x; bb[1] = z0.y; bb[2] = z0.z; bb[3] = z0.w;
        bb[4] = z1.x; bb[5] = z1.y; bb[6] = z1.z; bb[7] = z1.w;
    }
#pragma unroll
    for (int i = 0; i < 8; i++) {
        int m = bm * 128 + ty * 8 + i;
        if (m < M) {
            float4 o0, o1;
            o0.x = acc[i][0] + bb[0]; o0.y = acc[i][1] + bb[1];
            o0.z = acc[i][2] + bb[2]; o0.w = acc[i][3] + bb[3];
            o1.x = acc[i][4] + bb[4]; o1.y = acc[i][5] + bb[5];
            o1.z = acc[i][6] + bb[6]; o1.w = acc[i][7] + bb[7];
            if (relu) {
                o0.x = fmaxf(o0.x, 0.f); o0.y = fmaxf(o0.y, 0.f);
                o0.z = fmaxf(o0.z, 0.f); o0.w = fmaxf(o0.w, 0.f);
                o1.x = fmaxf(o1.x, 0.f); o1.y = fmaxf(o1.y, 0.f);
                o1.z = fmaxf(o1.z, 0.f); o1.w = fmaxf(o1.w, 0.f);
            }
            float* cp = C + (size_t)m * N + bn * 128 + tx * 8;
            *(float4*)cp = o0;
            *(float4*)(cp + 4) = o1;
        }
    }
}

// ---------------- decode ----------------
__global__ void decode_kernel(const int* __restrict__ ls,
                              const int* __restrict__ ld,
                              float* __restrict__ out) {
    int gt = blockIdx.x * blockDim.x + threadIdx.x;
    int i = gt >> 5;
    int lane = gt & 31;
    if (i >= NL) return;
    int a = __ldg(ls + i);
    int b = __ldg(ld + i);
    float4 u = ((const float4*)g_z_user)[a * 32 + lane];
    float4 v = ((const float4*)g_z_item)[b * 32 + lane];
    float s = u.x * v.x + u.y * v.y + u.z * v.z + u.w * v.w;
#pragma unroll
    for (int o = 16; o > 0; o >>= 1) s += __shfl_down_sync(0xffffffffu, s, o);
    if (lane == 0) {
        out[i] = -s;
        out[NL + i] = s;
    }
}

// ---------------- host launch ----------------
extern "C" void kernel_launch(void* const* d_in, const int* in_sizes, int n_in,
                              void* d_out, int out_size) {
    const float* x_user = (const float*)d_in[0];
    const float* x_item = (const float*)d_in[1];
    const float* Wl1_ui = (const float*)d_in[2];
    const float* Wr1_ui = (const float*)d_in[3];
    const float* b1_ui  = (const float*)d_in[4];
    const float* Wl1_iu = (const float*)d_in[5];
    const float* Wr1_iu = (const float*)d_in[6];
    const float* b1_iu  = (const float*)d_in[7];
    const float* Wl2_ui = (const float*)d_in[8];
    const float* Wr2_ui = (const float*)d_in[9];
    const float* b2_ui  = (const float*)d_in[10];
    const float* Wl2_iu = (const float*)d_in[11];
    const float* Wr2_iu = (const float*)d_in[12];
    const float* b2_iu  = (const float*)d_in[13];
    const int* src_u     = (const int*)d_in[14];
    const int* dst_i     = (const int*)d_in[15];
    const int* label_src = (const int*)d_in[16];
    const int* label_dst = (const int*)d_in[17];

    float *deg_u, *deg_i, *a1i, *a1u, *hi, *hu, *a2i, *a2u, *zi, *zu;
    cudaGetSymbolAddress((void**)&deg_u, g_deg_user);
    cudaGetSymbolAddress((void**)&deg_i, g_deg_item);
    cudaGetSymbolAddress((void**)&a1i, g_agg1_item);
    cudaGetSymbolAddress((void**)&a1u, g_agg1_user);
    cudaGetSymbolAddress((void**)&hi, g_h_item);
    cudaGetSymbolAddress((void**)&hu, g_h_user);
    cudaGetSymbolAddress((void**)&a2i, g_agg2_item);
    cudaGetSymbolAddress((void**)&a2u, g_agg2_user);
    cudaGetSymbolAddress((void**)&zi, g_z_item);
    cudaGetSymbolAddress((void**)&zu, g_z_user);

    // launch 0: zero layer-1 accumulators + degree counters (one fused launch)
    {
        int n0 = N_ITEM * D_IN / 4, n1 = N_USER * D_IN / 4;
        int n2 = N_USER / 4, n3 = N_ITEM / 4;
        int nmax = n1;
        zero_multi<<<(nmax + 255) / 256, 256>>>((float4*)a1i, n0, (float4*)a1u, n1,
                                                (float4*)deg_u, n2, (float4*)deg_i, n3);
    }

    // launch 1: layer-1 scatter + degrees
    {
        long long threads = (long long)NE * 32;
        scatter_l1<<<(int)((threads + 255) / 256), 256>>>(x_user, x_item, src_u, dst_i);
    }

    // launch 2: invert degrees
    invdeg_kernel<<<(N_USER + 255) / 256, 256>>>();

    // launch 3: zero layer-2 accumulators (independent of gemms)
    {
        int n0 = N_ITEM * D_HID / 4, n1 = N_USER * D_HID / 4;
        zero_multi<<<(n1 + 255) / 256, 256>>>((float4*)a2i, n0, (float4*)a2u, n1,
                                              nullptr, 0, nullptr, 0);
    }

    // launch 4: layer-1 item GEMM (K=128 per branch, N=256), relu
    gemm_fused<128, 256><<<dim3(2, (N_ITEM + 127) / 128), 256>>>(
        N_ITEM, a1i, deg_i, x_item, Wl1_ui, Wr1_ui, b1_ui, hi, 1);

    // launch 5 (ncu -s 5 -c 1 captures this): layer-1 user GEMM (the big one)
    gemm_fused<128, 256><<<dim3(2, (N_USER + 127) / 128), 256>>>(
        N_USER, a1u, deg_u, x_user, Wl1_iu, Wr1_iu, b1_iu, hu, 1);

    // launch 6: layer-2 scatter (256-dim)
    {
        long long threads = (long long)NE * 32;
        scatter_l2<<<(int)((threads + 255) / 256), 256>>>(src_u, dst_i);
    }

    // launches 7-8: layer-2 GEMMs (K=256 per branch, N=128), no relu
    gemm_fused<256, 128><<<dim3(1, (N_ITEM + 127) / 128), 256>>>(
        N_ITEM, a2i, deg_i, hi, Wl2_ui, Wr2_ui, b2_ui, zi, 0);
    gemm_fused<256, 128><<<dim3(1, (N_USER + 127) / 128), 256>>>(
        N_USER, a2u, deg_u, hu, Wl2_iu, Wr2_iu, b2_iu, zu, 0);

    // launch 9: decode
    {
        long long threads = (long long)NL * 32;
        decode_kernel<<<(int)((threads + 255) / 256), 256>>>(label_src, label_dst, (float*)d_out);
    }
}

// round 3
// speedup vs baseline: 1.9782x; 1.3056x over previous
#include <cuda_runtime.h>
#include <cstdint>
#include <cstddef>

#define N_USER 50000
#define N_ITEM 20000
#define D_IN   128
#define D_HID  256
#define D_OUT  128
#define NE     300000
#define NL     200000

// ---------------- device scratch (static, allocation-free) ----------------
__device__ float g_deg_user[N_USER];
__device__ float g_deg_item[N_ITEM];
__device__ float g_agg1_item[N_ITEM * D_IN];   // later reused as p_item
__device__ float g_agg1_user[N_USER * D_IN];   // later reused as p_user
__device__ float g_h_item[N_ITEM * D_HID];
__device__ float g_h_user[N_USER * D_HID];
__device__ float g_acc2_item[N_ITEM * D_OUT];  // 128-dim scatter acc (transform-first)
__device__ float g_acc2_user[N_USER * D_OUT];
__device__ float g_z_item[N_ITEM * D_OUT];
__device__ float g_z_user[N_USER * D_OUT];

// ---------------- fused zero fill ----------------
__global__ void zero_multi(float4* p0, int n0, float4* p1, int n1,
                           float4* p2, int n2, float4* p3, int n3) {
    int i = blockIdx.x * blockDim.x + threadIdx.x;
    float4 z = make_float4(0.f, 0.f, 0.f, 0.f);
    if (i < n0) p0[i] = z;
    if (i < n1) p1[i] = z;
    if (i < n2) p2[i] = z;
    if (i < n3) p3[i] = z;
}

// ---------------- vectorized global reduction ----------------
__device__ __forceinline__ void red_add_v4(float* p, float4 v) {
    asm volatile("red.global.add.v4.f32 [%0], {%1, %2, %3, %4};"
                 :: "l"(p), "f"(v.x), "f"(v.y), "f"(v.z), "f"(v.w)
                 : "memory");
}

// ---------------- layer-1 edge scatter (128-dim) + degree count ----------------
__global__ void scatter_l1(const float* __restrict__ x_user,
                           const float* __restrict__ x_item,
                           const int* __restrict__ src,
                           const int* __restrict__ dst) {
    int gt = blockIdx.x * blockDim.x + threadIdx.x;
    int e = gt >> 5;
    int lane = gt & 31;
    if (e >= NE) return;
    int s = __ldg(src + e);
    int d = __ldg(dst + e);

    float4 vu = __ldg(&((const float4*)x_user)[s * 32 + lane]);
    red_add_v4(g_agg1_item + d * 128 + lane * 4, vu);

    float4 vi = __ldg(&((const float4*)x_item)[d * 32 + lane]);
    red_add_v4(g_agg1_user + s * 128 + lane * 4, vi);

    if (lane == 0) {
        atomicAdd(&g_deg_item[d], 1.f);
        atomicAdd(&g_deg_user[s], 1.f);
    }
}

// ---------------- invert degrees ----------------
__global__ void invdeg_kernel() {
    int i = blockIdx.x * blockDim.x + threadIdx.x;
    if (i < N_USER) g_deg_user[i] = 1.f / fmaxf(g_deg_user[i], 1.f);
    if (i < N_ITEM) g_deg_item[i] = 1.f / fmaxf(g_deg_item[i], 1.f);
}

// ---------------- layer-2 scatter of transformed features (128-dim) ----------------
__global__ void scatter_p(const int* __restrict__ src,
                          const int* __restrict__ dst) {
    int gt = blockIdx.x * blockDim.x + threadIdx.x;
    int e = gt >> 5;
    int lane = gt & 31;
    if (e >= NE) return;
    int s = __ldg(src + e);
    int d = __ldg(dst + e);

    // p_user lives in g_agg1_user, p_item in g_agg1_item (buffer reuse)
    float4 pu = __ldg(&((const float4*)g_agg1_user)[s * 32 + lane]);
    red_add_v4(g_acc2_item + d * 128 + lane * 4, pu);

    float4 pi = __ldg(&((const float4*)g_agg1_item)[d * 32 + lane]);
    red_add_v4(g_acc2_user + s * 128 + lane * 4, pi);
}

// ---------------- 3xTF32 tensor-core GEMM ----------------
// C = [seg0: (A1 * invd_row) @ W1] + [seg1: A2 @ W2] + bias + Cin*invd_row, relu opt.
// A: [M, K] row-major per segment. W: [K, N] row-major. BM=BN=128, BK=8.
// 256 threads = 8 warps, warp tile 64x32 (4x4 grid of m16n8k8 mma).
__device__ __forceinline__ uint32_t f2tf(float f) {
    uint32_t u;
    asm("cvt.rna.tf32.f32 %0, %1;" : "=r"(u) : "f"(f));
    return u;
}

__device__ __forceinline__ void mma_tf32(float c[4],
                                         const uint32_t a[4],
                                         const uint32_t b[2]) {
    asm volatile(
        "mma.sync.aligned.m16n8k8.row.col.f32.tf32.tf32.f32 "
        "{%0,%1,%2,%3}, {%4,%5,%6,%7}, {%8,%9}, {%0,%1,%2,%3};"
        : "+f"(c[0]), "+f"(c[1]), "+f"(c[2]), "+f"(c[3])
        : "r"(a[0]), "r"(a[1]), "r"(a[2]), "r"(a[3]), "r"(b[0]), "r"(b[1]));
}

template <int K, int N, int NSEG, bool SCALE1, bool HASBIAS, bool CACC, bool RELU>
__global__ __launch_bounds__(256, 1)
void gemm_tf32(int M,
               const float* __restrict__ A1, const float* __restrict__ A2,
               const float* __restrict__ W1, const float* __restrict__ W2,
               const float* __restrict__ bias, const float* __restrict__ invd,
               const float* __restrict__ Cin, float* __restrict__ Cout) {
    __shared__ float AsH[2][128][12];   // [m][k], pad 12 -> conflict-free frag loads
    __shared__ float AsL[2][128][12];
    __shared__ float BsH[2][8][132];    // [k][n], pad 132
    __shared__ float BsL[2][8][132];

    const int tid = threadIdx.x;
    const int lane = tid & 31;
    const int w = tid >> 5;
    const int wm = (w & 1) * 64;
    const int wn = (w >> 1) * 32;
    const int bm = blockIdx.y * 128;
    const int bn = blockIdx.x * 128;

    const int fg = lane >> 2;   // group 0..7
    const int ft = lane & 3;    // 0..3

    // global->smem load mapping
    const int arow = tid >> 1;          // 0..127
    const int acol = (tid & 1) * 4;     // 0 or 4
    const int am = bm + arow;
    const int brow = tid >> 5;          // 0..7
    const int bcol = (tid & 31) * 4;    // 0..124

    float ascale = 1.f;
    if (SCALE1) ascale = (am < M) ? __ldg(invd + am) : 0.f;

    float acc[4][4][4];
#pragma unroll
    for (int i = 0; i < 4; i++)
#pragma unroll
        for (int j = 0; j < 4; j++)
#pragma unroll
            for (int r = 0; r < 4; r++) acc[i][j][r] = 0.f;

    const int TPS = K / 8;
    const int NT = NSEG * TPS;

    auto ldg_tile = [&](int t, float4& av, float4& bv) {
        const int seg = (NSEG == 2 && t >= TPS) ? 1 : 0;
        const float* A = seg ? A2 : A1;
        const float* W = seg ? W2 : W1;
        const int k0 = (t - seg * TPS) * 8;
        av = make_float4(0.f, 0.f, 0.f, 0.f);
        if (am < M) {
            av = *(const float4*)(A + (size_t)am * K + k0 + acol);
            if (SCALE1 && seg == 0) {
                av.x *= ascale; av.y *= ascale; av.z *= ascale; av.w *= ascale;
            }
        }
        bv = *(const float4*)(W + (size_t)(k0 + brow) * N + bn + bcol);
    };

    auto sts_tile = [&](int buf, float4 av, float4 bv) {
        float4 h;
        h.x = __uint_as_float(f2tf(av.x));
        h.y = __uint_as_float(f2tf(av.y));
        h.z = __uint_as_float(f2tf(av.z));
        h.w = __uint_as_float(f2tf(av.w));
        *(float4*)&AsH[buf][arow][acol] = h;
        *(float4*)&AsL[buf][arow][acol] =
            make_float4(av.x - h.x, av.y - h.y, av.z - h.z, av.w - h.w);
        float4 g;
        g.x = __uint_as_float(f2tf(bv.x));
        g.y = __uint_as_float(f2tf(bv.y));
        g.z = __uint_as_float(f2tf(bv.z));
        g.w = __uint_as_float(f2tf(bv.w));
        *(float4*)&BsH[buf][brow][bcol] = g;
        *(float4*)&BsL[buf][brow][bcol] =
            make_float4(bv.x - g.x, bv.y - g.y, bv.z - g.z, bv.w - g.w);
    };

    {
        float4 av, bv;
        ldg_tile(0, av, bv);
        sts_tile(0, av, bv);
    }
    __syncthreads();

    int buf = 0;
    for (int t = 0; t < NT; t++) {
        const bool more = (t + 1) < NT;
        float4 nav, nbv;
        if (more) ldg_tile(t + 1, nav, nbv);

        uint32_t ah[4][4], al[4][4], bh[4][2], bl[4][2];
#pragma unroll
        for (int mt = 0; mt < 4; mt++) {
            const int r = wm + 16 * mt + fg;
            ah[mt][0] = __float_as_uint(AsH[buf][r][ft]);
            ah[mt][1] = __float_as_uint(AsH[buf][r + 8][ft]);
            ah[mt][2] = __float_as_uint(AsH[buf][r][ft + 4]);
            ah[mt][3] = __float_as_uint(AsH[buf][r + 8][ft + 4]);
        }
#pragma unroll
        for (int nt = 0; nt < 4; nt++) {
            const int c = wn + 8 * nt + fg;
            bh[nt][0] = __float_as_uint(BsH[buf][ft][c]);
            bh[nt][1] = __float_as_uint(BsH[buf][ft + 4][c]);
        }
        // pass 1: Ah * Bh
#pragma unroll
        for (int mt = 0; mt < 4; mt++)
#pragma unroll
            for (int nt = 0; nt < 4; nt++) mma_tf32(acc[mt][nt], ah[mt], bh[nt]);

#pragma unroll
        for (int nt = 0; nt < 4; nt++) {
            const int c = wn + 8 * nt + fg;
            bl[nt][0] = __float_as_uint(BsL[buf][ft][c]);
            bl[nt][1] = __float_as_uint(BsL[buf][ft + 4][c]);
        }
        // pass 2: Ah * Bl
#pragma unroll
        for (int mt = 0; mt < 4; mt++)
#pragma unroll
            for (int nt = 0; nt < 4; nt++) mma_tf32(acc[mt][nt], ah[mt], bl[nt]);

#pragma unroll
        for (int mt = 0; mt < 4; mt++) {
            const int r = wm + 16 * mt + fg;
            al[mt][0] = __float_as_uint(AsL[buf][r][ft]);
            al[mt][1] = __float_as_uint(AsL[buf][r + 8][ft]);
            al[mt][2] = __float_as_uint(AsL[buf][r][ft + 4]);
            al[mt][3] = __float_as_uint(AsL[buf][r + 8][ft + 4]);
        }
        // pass 3: Al * Bh
#pragma unroll
        for (int mt = 0; mt < 4; mt++)
#pragma unroll
            for (int nt = 0; nt < 4; nt++) mma_tf32(acc[mt][nt], al[mt], bh[nt]);

        if (more) {
            sts_tile(buf ^ 1, nav, nbv);
            __syncthreads();
            buf ^= 1;
        }
    }

    // ---------------- epilogue ----------------
#pragma unroll
    for (int nt = 0; nt < 4; nt++) {
        const int c0 = bn + wn + 8 * nt + 2 * ft;
        float b0 = 0.f, b1 = 0.f;
        if (HASBIAS) {
            b0 = __ldg(bias + c0);
            b1 = __ldg(bias + c0 + 1);
        }
#pragma unroll
        for (int mt = 0; mt < 4; mt++) {
            const int r0 = bm + wm + 16 * mt + fg;
            const int r1 = r0 + 8;
            float o00 = acc[mt][nt][0] + b0;
            float o01 = acc[mt][nt][1] + b1;
            float o10 = acc[mt][nt][2] + b0;
            float o11 = acc[mt][nt][3] + b1;
            if (CACC) {
                if (r0 < M) {
                    float id0 = __ldg(invd + r0);
                    float2 ci = *(const float2*)(Cin + (size_t)r0 * N + c0);
                    o00 += ci.x * id0;
                    o01 += ci.y * id0;
                }
                if (r1 < M) {
                    float id1 = __ldg(invd + r1);
                    float2 ci = *(const float2*)(Cin + (size_t)r1 * N + c0);
                    o10 += ci.x * id1;
                    o11 += ci.y * id1;
                }
            }
            if (RELU) {
                o00 = fmaxf(o00, 0.f);
                o01 = fmaxf(o01, 0.f);
                o10 = fmaxf(o10, 0.f);
                o11 = fmaxf(o11, 0.f);
            }
            if (r0 < M) *(float2*)(Cout + (size_t)r0 * N + c0) = make_float2(o00, o01);
            if (r1 < M) *(float2*)(Cout + (size_t)r1 * N + c0) = make_float2(o10, o11);
        }
    }
}

// ---------------- decode ----------------
__global__ void decode_kernel(const int* __restrict__ ls,
                              const int* __restrict__ ld,
                              float* __restrict__ out) {
    int gt = blockIdx.x * blockDim.x + threadIdx.x;
    int i = gt >> 5;
    int lane = gt & 31;
    if (i >= NL) return;
    int a = __ldg(ls + i);
    int b = __ldg(ld + i);
    float4 u = ((const float4*)g_z_user)[a * 32 + lane];
    float4 v = ((const float4*)g_z_item)[b * 32 + lane];
    float s = u.x * v.x + u.y * v.y + u.z * v.z + u.w * v.w;
#pragma unroll
    for (int o = 16; o > 0; o >>= 1) s += __shfl_down_sync(0xffffffffu, s, o);
    if (lane == 0) {
        out[i] = -s;
        out[NL + i] = s;
    }
}

// ---------------- host launch ----------------
extern "C" void kernel_launch(void* const* d_in, const int* in_sizes, int n_in,
                              void* d_out, int out_size) {
    const float* x_user = (const float*)d_in[0];
    const float* x_item = (const float*)d_in[1];
    const float* Wl1_ui = (const float*)d_in[2];
    const float* Wr1_ui = (const float*)d_in[3];
    const float* b1_ui  = (const float*)d_in[4];
    const float* Wl1_iu = (const float*)d_in[5];
    const float* Wr1_iu = (const float*)d_in[6];
    const float* b1_iu  = (const float*)d_in[7];
    const float* Wl2_ui = (const float*)d_in[8];
    const float* Wr2_ui = (const float*)d_in[9];
    const float* b2_ui  = (const float*)d_in[10];
    const float* Wl2_iu = (const float*)d_in[11];
    const float* Wr2_iu = (const float*)d_in[12];
    const float* b2_iu  = (const float*)d_in[13];
    const int* src_u     = (const int*)d_in[14];
    const int* dst_i     = (const int*)d_in[15];
    const int* label_src = (const int*)d_in[16];
    const int* label_dst = (const int*)d_in[17];

    float *deg_u, *deg_i, *a1i, *a1u, *hi, *hu, *c2i, *c2u, *zi, *zu;
    cudaGetSymbolAddress((void**)&deg_u, g_deg_user);
    cudaGetSymbolAddress((void**)&deg_i, g_deg_item);
    cudaGetSymbolAddress((void**)&a1i, g_agg1_item);
    cudaGetSymbolAddress((void**)&a1u, g_agg1_user);
    cudaGetSymbolAddress((void**)&hi, g_h_item);
    cudaGetSymbolAddress((void**)&hu, g_h_user);
    cudaGetSymbolAddress((void**)&c2i, g_acc2_item);
    cudaGetSymbolAddress((void**)&c2u, g_acc2_user);
    cudaGetSymbolAddress((void**)&zi, g_z_item);
    cudaGetSymbolAddress((void**)&zu, g_z_user);

    // idx0: zero layer-1 accumulators + degree counters
    {
        int n0 = N_ITEM * D_IN / 4, n1 = N_USER * D_IN / 4;
        int n2 = N_USER / 4, n3 = N_ITEM / 4;
        zero_multi<<<(n1 + 255) / 256, 256>>>((float4*)a1i, n0, (float4*)a1u, n1,
                                              (float4*)deg_u, n2, (float4*)deg_i, n3);
    }

    // idx1: layer-1 scatter + degrees
    {
        long long threads = (long long)NE * 32;
        scatter_l1<<<(int)((threads + 255) / 256), 256>>>(x_user, x_item, src_u, dst_i);
    }

    // idx2: invert degrees
    invdeg_kernel<<<(N_USER + 255) / 256, 256>>>();

    // idx3 (profiler capture slot): layer-1 user GEMM
    // h_user = relu( (agg1_user*invd) @ Wl1_iu + x_user @ Wr1_iu + b1_iu )
    gemm_tf32<128, 256, 2, true, true, false, true>
        <<<dim3(2, (N_USER + 127) / 128), 256>>>(
            N_USER, a1u, x_user, Wl1_iu, Wr1_iu, b1_iu, deg_u, nullptr, hu);

    // idx4: layer-1 item GEMM
    gemm_tf32<128, 256, 2, true, true, false, true>
        <<<dim3(2, (N_ITEM + 127) / 128), 256>>>(
            N_ITEM, a1i, x_item, Wl1_ui, Wr1_ui, b1_ui, deg_i, nullptr, hi);

    // idx5: zero layer-2 scatter accumulators (128-dim)
    {
        int n0 = N_ITEM * D_OUT / 4, n1 = N_USER * D_OUT / 4;
        zero_multi<<<(n1 + 255) / 256, 256>>>((float4*)c2i, n0, (float4*)c2u, n1,
                                              nullptr, 0, nullptr, 0);
    }

    // idx6: p_user = h_user @ Wl2_ui  (into reused agg1_user buffer)
    gemm_tf32<256, 128, 1, false, false, false, false>
        <<<dim3(1, (N_USER + 127) / 128), 256>>>(
            N_USER, hu, nullptr, Wl2_ui, nullptr, nullptr, nullptr, nullptr, a1u);

    // idx7: p_item = h_item @ Wl2_iu  (into reused agg1_item buffer)
    gemm_tf32<256, 128, 1, false, false, false, false>
        <<<dim3(1, (N_ITEM + 127) / 128), 256>>>(
            N_ITEM, hi, nullptr, Wl2_iu, nullptr, nullptr, nullptr, nullptr, a1i);

    // idx8: layer-2 scatter of transformed features (128-dim)
    {
        long long threads = (long long)NE * 32;
        scatter_p<<<(int)((threads + 255) / 256), 256>>>(src_u, dst_i);
    }

    // idx9: z_item = acc2_item*invd_i + h_item @ Wr2_ui + b2_ui
    gemm_tf32<256, 128, 1, false, true, true, false>
        <<<dim3(1, (N_ITEM + 127) / 128), 256>>>(
            N_ITEM, hi, nullptr, Wr2_ui, nullptr, b2_ui, deg_i, c2i, zi);

    // idx10: z_user = acc2_user*invd_u + h_user @ Wr2_iu + b2_iu
    gemm_tf32<256, 128, 1, false, true, true, false>
        <<<dim3(1, (N_USER + 127) / 128), 256>>>(
            N_USER, hu, nullptr, Wr2_iu, nullptr, b2_iu, deg_u, c2u, zu);

    // idx11: decode
    {
        long long threads = (long long)NL * 32;
        decode_kernel<<<(int)((threads + 255) / 256), 256>>>(label_src, label_dst, (float*)d_out);
    }
}

// round 4
// speedup vs baseline: 3.4657x; 1.7520x over previous
#include <cuda_runtime.h>
#include <cuda_bf16.h>
#include <cstdint>
#include <cstddef>

#define N_USER 50000
#define N_ITEM 20000
#define D_IN   128
#define D_HID  256
#define D_OUT  128
#define NE     300000
#define NL     200000

// ---------------- device scratch (static, allocation-free) ----------------
__device__ float g_deg_user[N_USER];
__device__ float g_deg_item[N_ITEM];
__device__ float g_agg1_item[N_ITEM * D_IN];   // later reused as p_item
__device__ float g_agg1_user[N_USER * D_IN];   // later reused as p_user
__device__ float g_h_item[N_ITEM * D_HID];
__device__ float g_h_user[N_USER * D_HID];
__device__ float g_acc2_item[N_ITEM * D_OUT];  // 128-dim scatter acc
__device__ float g_acc2_user[N_USER * D_OUT];
__device__ float g_z_item[N_ITEM * D_OUT];
__device__ float g_z_user[N_USER * D_OUT];

// ---------------- fused zero fill (6 buffers, one launch) ----------------
__global__ void zero_multi6(float4* p0, int n0, float4* p1, int n1,
                            float4* p2, int n2, float4* p3, int n3,
                            float4* p4, int n4, float4* p5, int n5) {
    int i = blockIdx.x * blockDim.x + threadIdx.x;
    float4 z = make_float4(0.f, 0.f, 0.f, 0.f);
    if (i < n0) p0[i] = z;
    if (i < n1) p1[i] = z;
    if (i < n2) p2[i] = z;
    if (i < n3) p3[i] = z;
    if (i < n4) p4[i] = z;
    if (i < n5) p5[i] = z;
}

// ---------------- vectorized global reduction ----------------
__device__ __forceinline__ void red_add_v4(float* p, float4 v) {
    asm volatile("red.global.add.v4.f32 [%0], {%1, %2, %3, %4};"
                 :: "l"(p), "f"(v.x), "f"(v.y), "f"(v.z), "f"(v.w)
                 : "memory");
}

// ---------------- layer-1 edge scatter (128-dim) + degree count ----------------
__global__ void scatter_l1(const float* __restrict__ x_user,
                           const float* __restrict__ x_item,
                           const int* __restrict__ src,
                           const int* __restrict__ dst) {
    int gt = blockIdx.x * blockDim.x + threadIdx.x;
    int e = gt >> 5;
    int lane = gt & 31;
    if (e >= NE) return;
    int s = __ldg(src + e);
    int d = __ldg(dst + e);

    float4 vu = __ldg(&((const float4*)x_user)[s * 32 + lane]);
    red_add_v4(g_agg1_item + d * 128 + lane * 4, vu);

    float4 vi = __ldg(&((const float4*)x_item)[d * 32 + lane]);
    red_add_v4(g_agg1_user + s * 128 + lane * 4, vi);

    if (lane == 0) {
        atomicAdd(&g_deg_item[d], 1.f);
        atomicAdd(&g_deg_user[s], 1.f);
    }
}

// ---------------- invert degrees ----------------
__global__ void invdeg_kernel() {
    int i = blockIdx.x * blockDim.x + threadIdx.x;
    if (i < N_USER) g_deg_user[i] = 1.f / fmaxf(g_deg_user[i], 1.f);
    if (i < N_ITEM) g_deg_item[i] = 1.f / fmaxf(g_deg_item[i], 1.f);
}

// ---------------- layer-2 scatter of transformed features (128-dim) ----------------
__global__ void scatter_p(const int* __restrict__ src,
                          const int* __restrict__ dst) {
    int gt = blockIdx.x * blockDim.x + threadIdx.x;
    int e = gt >> 5;
    int lane = gt & 31;
    if (e >= NE) return;
    int s = __ldg(src + e);
    int d = __ldg(dst + e);

    float4 pu = __ldg(&((const float4*)g_agg1_user)[s * 32 + lane]);
    red_add_v4(g_acc2_item + d * 128 + lane * 4, pu);

    float4 pi = __ldg(&((const float4*)g_agg1_item)[d * 32 + lane]);
    red_add_v4(g_acc2_user + s * 128 + lane * 4, pi);
}

// ---------------- 3xBF16 tensor-core GEMM ----------------
// C = [seg0: (A1 * invd_row) @ W1] + [seg1: A2 @ W2] + bias + Cin*invd_row, relu opt.
// BM=BN=128, BK=16, 256 threads (8 warps, 64x32 warp tiles), 2 CTAs/SM.
__device__ __forceinline__ void split2(float x0, float x1, uint32_t& hi, uint32_t& lo) {
    __nv_bfloat162 h = __floats2bfloat162_rn(x0, x1);   // .x = x0 (low half)
    float r0 = x0 - __bfloat162float(__low2bfloat16(h));
    float r1 = x1 - __bfloat162float(__high2bfloat16(h));
    __nv_bfloat162 l = __floats2bfloat162_rn(r0, r1);
    hi = *reinterpret_cast<uint32_t*>(&h);
    lo = *reinterpret_cast<uint32_t*>(&l);
}

__device__ __forceinline__ void mma_bf16(float c[4],
                                         const uint32_t a[4],
                                         const uint32_t b[2]) {
    asm volatile(
        "mma.sync.aligned.m16n8k16.row.col.f32.bf16.bf16.f32 "
        "{%0,%1,%2,%3}, {%4,%5,%6,%7}, {%8,%9}, {%0,%1,%2,%3};"
        : "+f"(c[0]), "+f"(c[1]), "+f"(c[2]), "+f"(c[3])
        : "r"(a[0]), "r"(a[1]), "r"(a[2]), "r"(a[3]), "r"(b[0]), "r"(b[1]));
}

template <int K, int N, int NSEG, bool SCALE1, bool HASBIAS, bool CACC, bool RELU>
__global__ __launch_bounds__(256, 2)
void gemm_bf16x3(int M,
                 const float* __restrict__ A1, const float* __restrict__ A2,
                 const float* __restrict__ W1, const float* __restrict__ W2,
                 const float* __restrict__ bias, const float* __restrict__ invd,
                 const float* __restrict__ Cin, float* __restrict__ Cout) {
    // A: [m][k-pair] packed bf16x2; pad 12 words -> conflict-free frag loads
    __shared__ uint32_t AsH[2][128][12];
    __shared__ uint32_t AsL[2][128][12];
    // B: [k-pair][n] packed bf16x2; pad 136 (== 8 mod 32) -> conflict-free frag loads
    __shared__ uint32_t BsH[2][8][136];
    __shared__ uint32_t BsL[2][8][136];

    const int tid = threadIdx.x;
    const int lane = tid & 31;
    const int w = tid >> 5;
    const int wm = (w & 1) * 64;
    const int wn = (w >> 1) * 32;
    const int bm = blockIdx.y * 128;
    const int bn = blockIdx.x * 128;

    const int fg = lane >> 2;   // 0..7
    const int ft = lane & 3;    // 0..3

    // global->smem mapping
    const int arow = tid >> 1;            // 0..127
    const int ak8  = (tid & 1) * 8;       // 0 or 8 (k offset, 8 floats each)
    const int am = bm + arow;
    const int bk2 = tid >> 5;             // 0..7 (k-pair index)
    const int bn0 = (tid & 31) * 4;       // 0..124

    float ascale = 1.f;
    if (SCALE1) ascale = (am < M) ? __ldg(invd + am) : 0.f;

    float acc[4][4][4];
#pragma unroll
    for (int i = 0; i < 4; i++)
#pragma unroll
        for (int j = 0; j < 4; j++)
#pragma unroll
            for (int r = 0; r < 4; r++) acc[i][j][r] = 0.f;

    const int TPS = K / 16;
    const int NT = NSEG * TPS;

    auto ldg_tile = [&](int t, float4& a0, float4& a1, float4& b0, float4& b1) {
        const int seg = (NSEG == 2 && t >= TPS) ? 1 : 0;
        const float* A = seg ? A2 : A1;
        const float* W = seg ? W2 : W1;
        const int k0 = (t - seg * TPS) * 16;
        a0 = make_float4(0.f, 0.f, 0.f, 0.f);
        a1 = a0;
        if (am < M) {
            const float* ap = A + (size_t)am * K + k0 + ak8;
            a0 = *(const float4*)ap;
            a1 = *(const float4*)(ap + 4);
            if (SCALE1 && seg == 0) {
                a0.x *= ascale; a0.y *= ascale; a0.z *= ascale; a0.w *= ascale;
                a1.x *= ascale; a1.y *= ascale; a1.z *= ascale; a1.w *= ascale;
            }
        }
        const float* wp = W + (size_t)(k0 + 2 * bk2) * N + bn + bn0;
        b0 = *(const float4*)wp;         // k = k0+2*bk2
        b1 = *(const float4*)(wp + N);   // k = k0+2*bk2+1
    };

    auto sts_tile = [&](int buf, float4 a0, float4 a1, float4 b0, float4 b1) {
        // A: pack pairs along k
        uint4 h, l;
        split2(a0.x, a0.y, h.x, l.x);
        split2(a0.z, a0.w, h.y, l.y);
        split2(a1.x, a1.y, h.z, l.z);
        split2(a1.z, a1.w, h.w, l.w);
        *(uint4*)&AsH[buf][arow][(ak8 >> 1)] = h;
        *(uint4*)&AsL[buf][arow][(ak8 >> 1)] = l;
        // B: pair (k even, k odd) for each of 4 consecutive n
        uint4 bh4, bl4;
        split2(b0.x, b1.x, bh4.x, bl4.x);
        split2(b0.y, b1.y, bh4.y, bl4.y);
        split2(b0.z, b1.z, bh4.z, bl4.z);
        split2(b0.w, b1.w, bh4.w, bl4.w);
        *(uint4*)&BsH[buf][bk2][bn0] = bh4;
        *(uint4*)&BsL[buf][bk2][bn0] = bl4;
    };

    {
        float4 a0, a1, b0, b1;
        ldg_tile(0, a0, a1, b0, b1);
        sts_tile(0, a0, a1, b0, b1);
    }
    __syncthreads();

    int buf = 0;
    for (int t = 0; t < NT; t++) {
        const bool more = (t + 1) < NT;
        float4 na0, na1, nb0, nb1;
        if (more) ldg_tile(t + 1, na0, na1, nb0, nb1);

        uint32_t ah[4][4], al[4][4], bh[4][2], bl[4][2];
#pragma unroll
        for (int mt = 0; mt < 4; mt++) {
            const int r = wm + 16 * mt + fg;
            ah[mt][0] = AsH[buf][r][ft];
            ah[mt][1] = AsH[buf][r + 8][ft];
            ah[mt][2] = AsH[buf][r][ft + 4];
            ah[mt][3] = AsH[buf][r + 8][ft + 4];
        }
#pragma unroll
        for (int nt = 0; nt < 4; nt++) {
            const int c = wn + 8 * nt + fg;
            bh[nt][0] = BsH[buf][ft][c];
            bh[nt][1] = BsH[buf][ft + 4][c];
        }
        // pass 1: Ah * Bh
#pragma unroll
        for (int mt = 0; mt < 4; mt++)
#pragma unroll
            for (int nt = 0; nt < 4; nt++) mma_bf16(acc[mt][nt], ah[mt], bh[nt]);

#pragma unroll
        for (int mt = 0; mt < 4; mt++) {
            const int r = wm + 16 * mt + fg;
            al[mt][0] = AsL[buf][r][ft];
            al[mt][1] = AsL[buf][r + 8][ft];
            al[mt][2] = AsL[buf][r][ft + 4];
            al[mt][3] = AsL[buf][r + 8][ft + 4];
        }
        // pass 2: Al * Bh
#pragma unroll
        for (int mt = 0; mt < 4; mt++)
#pragma unroll
            for (int nt = 0; nt < 4; nt++) mma_bf16(acc[mt][nt], al[mt], bh[nt]);

#pragma unroll
        for (int nt = 0; nt < 4; nt++) {
            const int c = wn + 8 * nt + fg;
            bl[nt][0] = BsL[buf][ft][c];
            bl[nt][1] = BsL[buf][ft + 4][c];
        }
        // pass 3: Ah * Bl
#pragma unroll
        for (int mt = 0; mt < 4; mt++)
#pragma unroll
            for (int nt = 0; nt < 4; nt++) mma_bf16(acc[mt][nt], ah[mt], bl[nt]);

        if (more) {
            sts_tile(buf ^ 1, na0, na1, nb0, nb1);
            __syncthreads();
            buf ^= 1;
        }
    }

    // ---------------- epilogue ----------------
#pragma unroll
    for (int nt = 0; nt < 4; nt++) {
        const int c0 = bn + wn + 8 * nt + 2 * ft;
        float b0 = 0.f, b1 = 0.f;
        if (HASBIAS) {
            b0 = __ldg(bias + c0);
            b1 = __ldg(bias + c0 + 1);
        }
#pragma unroll
        for (int mt = 0; mt < 4; mt++) {
            const int r0 = bm + wm + 16 * mt + fg;
            const int r1 = r0 + 8;
            float o00 = acc[mt][nt][0] + b0;
            float o01 = acc[mt][nt][1] + b1;
            float o10 = acc[mt][nt][2] + b0;
            float o11 = acc[mt][nt][3] + b1;
            if (CACC) {
                if (r0 < M) {
                    float id0 = __ldg(invd + r0);
                    float2 ci = *(const float2*)(Cin + (size_t)r0 * N + c0);
                    o00 += ci.x * id0;
                    o01 += ci.y * id0;
                }
                if (r1 < M) {
                    float id1 = __ldg(invd + r1);
                    float2 ci = *(const float2*)(Cin + (size_t)r1 * N + c0);
                    o10 += ci.x * id1;
                    o11 += ci.y * id1;
                }
            }
            if (RELU) {
                o00 = fmaxf(o00, 0.f);
                o01 = fmaxf(o01, 0.f);
                o10 = fmaxf(o10, 0.f);
                o11 = fmaxf(o11, 0.f);
            }
            if (r0 < M) *(float2*)(Cout + (size_t)r0 * N + c0) = make_float2(o00, o01);
            if (r1 < M) *(float2*)(Cout + (size_t)r1 * N + c0) = make_float2(o10, o11);
        }
    }
}

// ---------------- decode ----------------
__global__ void decode_kernel(const int* __restrict__ ls,
                              const int* __restrict__ ld,
                              float* __restrict__ out) {
    int gt = blockIdx.x * blockDim.x + threadIdx.x;
    int i = gt >> 5;
    int lane = gt & 31;
    if (i >= NL) return;
    int a = __ldg(ls + i);
    int b = __ldg(ld + i);
    float4 u = ((const float4*)g_z_user)[a * 32 + lane];
    float4 v = ((const float4*)g_z_item)[b * 32 + lane];
    float s = u.x * v.x + u.y * v.y + u.z * v.z + u.w * v.w;
#pragma unroll
    for (int o = 16; o > 0; o >>= 1) s += __shfl_down_sync(0xffffffffu, s, o);
    if (lane == 0) {
        out[i] = -s;
        out[NL + i] = s;
    }
}

// ---------------- host launch ----------------
extern "C" void kernel_launch(void* const* d_in, const int* in_sizes, int n_in,
                              void* d_out, int out_size) {
    const float* x_user = (const float*)d_in[0];
    const float* x_item = (const float*)d_in[1];
    const float* Wl1_ui = (const float*)d_in[2];
    const float* Wr1_ui = (const float*)d_in[3];
    const float* b1_ui  = (const float*)d_in[4];
    const float* Wl1_iu = (const float*)d_in[5];
    const float* Wr1_iu = (const float*)d_in[6];
    const float* b1_iu  = (const float*)d_in[7];
    const float* Wl2_ui = (const float*)d_in[8];
    const float* Wr2_ui = (const float*)d_in[9];
    const float* b2_ui  = (const float*)d_in[10];
    const float* Wl2_iu = (const float*)d_in[11];
    const float* Wr2_iu = (const float*)d_in[12];
    const float* b2_iu  = (const float*)d_in[13];
    const int* src_u     = (const int*)d_in[14];
    const int* dst_i     = (const int*)d_in[15];
    const int* label_src = (const int*)d_in[16];
    const int* label_dst = (const int*)d_in[17];

    float *deg_u, *deg_i, *a1i, *a1u, *hi, *hu, *c2i, *c2u, *zi, *zu;
    cudaGetSymbolAddress((void**)&deg_u, g_deg_user);
    cudaGetSymbolAddress((void**)&deg_i, g_deg_item);
    cudaGetSymbolAddress((void**)&a1i, g_agg1_item);
    cudaGetSymbolAddress((void**)&a1u, g_agg1_user);
    cudaGetSymbolAddress((void**)&hi, g_h_item);
    cudaGetSymbolAddress((void**)&hu, g_h_user);
    cudaGetSymbolAddress((void**)&c2i, g_acc2_item);
    cudaGetSymbolAddress((void**)&c2u, g_acc2_user);
    cudaGetSymbolAddress((void**)&zi, g_z_item);
    cudaGetSymbolAddress((void**)&zu, g_z_user);

    // idx0: zero all accumulators + degree counters (single launch)
    {
        int n0 = N_ITEM * D_IN / 4, n1 = N_USER * D_IN / 4;
        int n2 = N_USER / 4, n3 = N_ITEM / 4;
        int n4 = N_ITEM * D_OUT / 4, n5 = N_USER * D_OUT / 4;
        zero_multi6<<<(n1 + 255) / 256, 256>>>((float4*)a1i, n0, (float4*)a1u, n1,
                                               (float4*)deg_u, n2, (float4*)deg_i, n3,
                                               (float4*)c2i, n4, (float4*)c2u, n5);
    }

    // idx1: layer-1 scatter + degrees
    {
        long long threads = (long long)NE * 32;
        scatter_l1<<<(int)((threads + 255) / 256), 256>>>(x_user, x_item, src_u, dst_i);
    }

    // idx2: invert degrees
    invdeg_kernel<<<(N_USER + 255) / 256, 256>>>();

    // idx3 (profiler capture slot): layer-1 user GEMM
    gemm_bf16x3<128, 256, 2, true, true, false, true>
        <<<dim3(2, (N_USER + 127) / 128), 256>>>(
            N_USER, a1u, x_user, Wl1_iu, Wr1_iu, b1_iu, deg_u, nullptr, hu);

    // idx4: layer-1 item GEMM
    gemm_bf16x3<128, 256, 2, true, true, false, true>
        <<<dim3(2, (N_ITEM + 127) / 128), 256>>>(
            N_ITEM, a1i, x_item, Wl1_ui, Wr1_ui, b1_ui, deg_i, nullptr, hi);

    // idx5: p_user = h_user @ Wl2_ui  (into reused agg1_user buffer)
    gemm_bf16x3<256, 128, 1, false, false, false, false>
        <<<dim3(1, (N_USER + 127) / 128), 256>>>(
            N_USER, hu, nullptr, Wl2_ui, nullptr, nullptr, nullptr, nullptr, a1u);

    // idx6: p_item = h_item @ Wl2_iu  (into reused agg1_item buffer)
    gemm_bf16x3<256, 128, 1, false, false, false, false>
        <<<dim3(1, (N_ITEM + 127) / 128), 256>>>(
            N_ITEM, hi, nullptr, Wl2_iu, nullptr, nullptr, nullptr, nullptr, a1i);

    // idx7: layer-2 scatter of transformed features (128-dim)
    {
        long long threads = (long long)NE * 32;
        scatter_p<<<(int)((threads + 255) / 256), 256>>>(src_u, dst_i);
    }

    // idx8: z_item = acc2_item*invd_i + h_item @ Wr2_ui + b2_ui
    gemm_bf16x3<256, 128, 1, false, true, true, false>
        <<<dim3(1, (N_ITEM + 127) / 128), 256>>>(
            N_ITEM, hi, nullptr, Wr2_ui, nullptr, b2_ui, deg_i, c2i, zi);

    // idx9: z_user = acc2_user*invd_u + h_user @ Wr2_iu + b2_iu
    gemm_bf16x3<256, 128, 1, false, true, true, false>
        <<<dim3(1, (N_USER + 127) / 128), 256>>>(
            N_USER, hu, nullptr, Wr2_iu, nullptr, b2_iu, deg_u, c2u, zu);

    // idx10: decode
    {
        long long threads = (long long)NL * 32;
        decode_kernel<<<(int)((threads + 255) / 256), 256>>>(label_src, label_dst, (float*)d_out);
    }
}

// round 6
// speedup vs baseline: 3.8295x; 1.1050x over previous
#include <cuda_runtime.h>
#include <cuda_bf16.h>
#include <cstdint>
#include <cstddef>

#define N_USER 50000
#define N_ITEM 20000
#define D_IN   128
#define D_HID  256
#define D_OUT  128
#define NE     300000
#define NL     200000

// ---------------- device scratch (static, allocation-free) ----------------
__device__ float g_deg_user[N_USER];
__device__ float g_deg_item[N_ITEM];
__device__ float g_agg1_item[N_ITEM * D_IN];   // later reused as p_item
__device__ float g_agg1_user[N_USER * D_IN];   // later reused as p_user
__device__ float g_h_item[N_ITEM * D_HID];
__device__ float g_h_user[N_USER * D_HID];
__device__ float g_acc2_item[N_ITEM * D_OUT];
__device__ float g_acc2_user[N_USER * D_OUT];
__device__ float g_z_item[N_ITEM * D_OUT];
__device__ float g_z_user[N_USER * D_OUT];
// weights pre-split to bf16 hi/lo: 8 matrices x 32768 elems each
__device__ __nv_bfloat16 g_whi[8 * 32768];
__device__ __nv_bfloat16 g_wlo[8 * 32768];

// ---------------- fused zero fill (6 buffers, one launch) ----------------
__global__ void zero_multi6(float4* p0, int n0, float4* p1, int n1,
                            float4* p2, int n2, float4* p3, int n3,
                            float4* p4, int n4, float4* p5, int n5) {
    int i = blockIdx.x * blockDim.x + threadIdx.x;
    float4 z = make_float4(0.f, 0.f, 0.f, 0.f);
    if (i < n0) p0[i] = z;
    if (i < n1) p1[i] = z;
    if (i < n2) p2[i] = z;
    if (i < n3) p3[i] = z;
    if (i < n4) p4[i] = z;
    if (i < n5) p5[i] = z;
}

// ---------------- weight pre-split: fp32 -> bf16 hi + bf16 lo ----------------
__global__ void wsplit_kernel(const float* w0, const float* w1, const float* w2,
                              const float* w3, const float* w4, const float* w5,
                              const float* w6, const float* w7) {
    int e = blockIdx.x * blockDim.x + threadIdx.x;  // 0..32767
    int w = blockIdx.y;                              // 0..7
    const float* src;
    switch (w) {
        case 0: src = w0; break;
        case 1: src = w1; break;
        case 2: src = w2; break;
        case 3: src = w3; break;
        case 4: src = w4; break;
        case 5: src = w5; break;
        case 6: src = w6; break;
        default: src = w7; break;
    }
    float v = src[e];
    __nv_bfloat16 h = __float2bfloat16(v);
    g_whi[w * 32768 + e] = h;
    g_wlo[w * 32768 + e] = __float2bfloat16(v - __bfloat162float(h));
}

// ---------------- vectorized global reduction ----------------
__device__ __forceinline__ void red_add_v4(float* p, float4 v) {
    asm volatile("red.global.add.v4.f32 [%0], {%1, %2, %3, %4};"
                 :: "l"(p), "f"(v.x), "f"(v.y), "f"(v.z), "f"(v.w)
                 : "memory");
}

// ---------------- layer-1 edge scatter (128-dim) + degree count ----------------
__global__ void scatter_l1(const float* __restrict__ x_user,
                           const float* __restrict__ x_item,
                           const int* __restrict__ src,
                           const int* __restrict__ dst) {
    int gt = blockIdx.x * blockDim.x + threadIdx.x;
    int e = gt >> 5;
    int lane = gt & 31;
    if (e >= NE) return;
    int s = __ldg(src + e);
    int d = __ldg(dst + e);

    float4 vu = __ldg(&((const float4*)x_user)[s * 32 + lane]);
    red_add_v4(g_agg1_item + d * 128 + lane * 4, vu);

    float4 vi = __ldg(&((const float4*)x_item)[d * 32 + lane]);
    red_add_v4(g_agg1_user + s * 128 + lane * 4, vi);

    if (lane == 0) {
        atomicAdd(&g_deg_item[d], 1.f);
        atomicAdd(&g_deg_user[s], 1.f);
    }
}

// ---------------- layer-2 scatter of transformed features (128-dim) ----------------
__global__ void scatter_p(const int* __restrict__ src,
                          const int* __restrict__ dst) {
    int gt = blockIdx.x * blockDim.x + threadIdx.x;
    int e = gt >> 5;
    int lane = gt & 31;
    if (e >= NE) return;
    int s = __ldg(src + e);
    int d = __ldg(dst + e);

    float4 pu = __ldg(&((const float4*)g_agg1_user)[s * 32 + lane]);
    red_add_v4(g_acc2_item + d * 128 + lane * 4, pu);

    float4 pi = __ldg(&((const float4*)g_agg1_item)[d * 32 + lane]);
    red_add_v4(g_acc2_user + s * 128 + lane * 4, pi);
}

// ================= 3xBF16 mma.sync GEMM (frag-major A, paired launch) =======
// Per side: C = [seg0: (A1/deg) @ W1] (+ seg1: A2 @ W2) + bias + Cin/deg, relu.
// BM=BN=128, BK=16, 256 threads (8 warps, 64x32 warp tiles), 2 CTAs/SM.
__device__ __forceinline__ void split2(float x0, float x1, uint32_t& hi, uint32_t& lo) {
    __nv_bfloat162 h = __floats2bfloat162_rn(x0, x1);
    float r0 = x0 - __bfloat162float(__low2bfloat16(h));
    float r1 = x1 - __bfloat162float(__high2bfloat16(h));
    __nv_bfloat162 l = __floats2bfloat162_rn(r0, r1);
    hi = *reinterpret_cast<uint32_t*>(&h);
    lo = *reinterpret_cast<uint32_t*>(&l);
}

__device__ __forceinline__ void mma_bf16(float c[4],
                                         const uint32_t a[4],
                                         const uint32_t b[2]) {
    asm volatile(
        "mma.sync.aligned.m16n8k16.row.col.f32.bf16.bf16.f32 "
        "{%0,%1,%2,%3}, {%4,%5,%6,%7}, {%8,%9}, {%0,%1,%2,%3};"
        : "+f"(c[0]), "+f"(c[1]), "+f"(c[2]), "+f"(c[3])
        : "r"(a[0]), "r"(a[1]), "r"(a[2]), "r"(a[3]), "r"(b[0]), "r"(b[1]));
}

struct GPair {
    int M[2];
    const float* A1[2];
    const float* A2[2];
    const __nv_bfloat16* W1h[2];
    const __nv_bfloat16* W1l[2];
    const __nv_bfloat16* W2h[2];
    const __nv_bfloat16* W2l[2];
    const float* bias[2];
    const float* deg[2];
    const float* Cin[2];
    float* C[2];
};

template <int K, int N, int NSEG, bool SCALE1, bool HASBIAS, bool CACC, bool RELU>
__global__ __launch_bounds__(256, 2)
void gemm_pair(GPair P) {
    const int side = blockIdx.z;
    const int M = P.M[side];
    const int bm = blockIdx.y * 128;
    if (bm >= M) return;
    const int bn = blockIdx.x * 128;

    const float* __restrict__ A1 = P.A1[side];
    const float* __restrict__ A2 = P.A2[side];
    const __nv_bfloat16* __restrict__ W1h = P.W1h[side];
    const __nv_bfloat16* __restrict__ W1l = P.W1l[side];
    const __nv_bfloat16* __restrict__ W2h = P.W2h[side];
    const __nv_bfloat16* __restrict__ W2l = P.W2l[side];
    const float* __restrict__ bias = P.bias[side];
    const float* __restrict__ deg = P.deg[side];
    const float* __restrict__ Cin = P.Cin[side];
    float* __restrict__ Cout = P.C[side];

    // A frag tuples: [wmblk 2][mt 4][fg 8][ft' 4][4 words] = 1024 words = 4KB
    __shared__ uint32_t AsH[2][1024];
    __shared__ uint32_t AsL[2][1024];
    // B pairs: [kp 8][n 136 pad] -> known conflict-free
    __shared__ uint32_t BsH[2][8][136];
    __shared__ uint32_t BsL[2][8][136];

    const int tid = threadIdx.x;
    const int lane = tid & 31;
    const int w = tid >> 5;
    const int wmblk = w & 1;
    const int wm = wmblk * 64;
    const int wn = (w >> 1) * 32;
    const int fg = lane >> 2;
    const int ft = lane & 3;
    const int ftp = ft ^ ((fg >> 1) & 3);   // swizzled tuple slot

    // ---- producer mappings ----
    // A: one thread per (row, k-half-of-16)
    const int arow = tid >> 1;
    const int khalf = tid & 1;
    const int am = bm + arow;
    const bool avalid = am < M;
    const int pwm = arow >> 6;
    const int pmt = (arow >> 4) & 3;
    const int pfg = arow & 7;
    const int prh = (arow >> 3) & 1;
    const int psw = (pfg >> 1) & 3;
    // B: one thread per (k-pair, 4 n)
    const int kp = tid >> 5;
    const int n0 = (lane) * 4;

    float ascale = 1.f;
    if (SCALE1) ascale = avalid ? (1.f / fmaxf(__ldg(deg + am), 1.f)) : 0.f;

    float acc[4][4][4];
#pragma unroll
    for (int i = 0; i < 4; i++)
#pragma unroll
        for (int j = 0; j < 4; j++)
#pragma unroll
            for (int r = 0; r < 4; r++) acc[i][j][r] = 0.f;

    const int TPS = K / 16;
    const int NT = NSEG * TPS;

    auto ldg_tile = [&](int t, float4& a0, float4& a1, uint2& bh0, uint2& bh1,
                        uint2& bl0, uint2& bl1) {
        const int seg = (NSEG == 2 && t >= TPS) ? 1 : 0;
        const int k0 = (t - seg * TPS) * 16;
        const float* A = seg ? A2 : A1;
        a0 = make_float4(0.f, 0.f, 0.f, 0.f);
        a1 = a0;
        if (avalid) {
            const float* ap = A + (size_t)am * K + k0 + khalf * 8;
            a0 = *(const float4*)ap;
            a1 = *(const float4*)(ap + 4);
            if (SCALE1 && seg == 0) {
                a0.x *= ascale; a0.y *= ascale; a0.z *= ascale; a0.w *= ascale;
                a1.x *= ascale; a1.y *= ascale; a1.z *= ascale; a1.w *= ascale;
            }
        }
        const __nv_bfloat16* Wh = seg ? W2h : W1h;
        const __nv_bfloat16* Wl = seg ? W2l : W1l;
        const __nv_bfloat16* wh = Wh + (size_t)(k0 + 2 * kp) * N + bn + n0;
        const __nv_bfloat16* wl = Wl + (size_t)(k0 + 2 * kp) * N + bn + n0;
        bh0 = *(const uint2*)wh;
        bh1 = *(const uint2*)(wh + N);
        bl0 = *(const uint2*)wl;
        bl1 = *(const uint2*)(wl + N);
    };

    auto sts_tile = [&](int s, float4 a0, float4 a1, uint2 bh0, uint2 bh1,
                        uint2 bl0, uint2 bl1) {
        // A: 4 pairs -> frag-major tuples (swizzled slot), 4+4 STS.32
        float f[8] = {a0.x, a0.y, a0.z, a0.w, a1.x, a1.y, a1.z, a1.w};
        const int tbase = ((pwm * 4 + pmt) * 8 + pfg) * 16 + prh * 2 + khalf;
#pragma unroll
        for (int j = 0; j < 4; j++) {
            uint32_t h, l;
            split2(f[2 * j], f[2 * j + 1], h, l);
            int widx = tbase + (j ^ psw) * 4;
            AsH[s][widx] = h;
            AsL[s][widx] = l;
        }
        // B: pack (k even, k odd) pairs for 4 consecutive n, 2 STS.128
        uint4 ph, pl;
        ph.x = __byte_perm(bh0.x, bh1.x, 0x5410);
        ph.y = __byte_perm(bh0.x, bh1.x, 0x7632);
        ph.z = __byte_perm(bh0.y, bh1.y, 0x5410);
        ph.w = __byte_perm(bh0.y, bh1.y, 0x7632);
        pl.x = __byte_perm(bl0.x, bl1.x, 0x5410);
        pl.y = __byte_perm(bl0.x, bl1.x, 0x7632);
        pl.z = __byte_perm(bl0.y, bl1.y, 0x5410);
        pl.w = __byte_perm(bl0.y, bl1.y, 0x7632);
        *(uint4*)&BsH[s][kp][n0] = ph;
        *(uint4*)&BsL[s][kp][n0] = pl;
    };

    {
        float4 a0, a1; uint2 bh0, bh1, bl0, bl1;
        ldg_tile(0, a0, a1, bh0, bh1, bl0, bl1);
        sts_tile(0, a0, a1, bh0, bh1, bl0, bl1);
    }
    __syncthreads();

    int buf = 0;
    for (int t = 0; t < NT; t++) {
        const bool more = (t + 1) < NT;
        float4 na0, na1; uint2 nbh0, nbh1, nbl0, nbl1;
        if (more) ldg_tile(t + 1, na0, na1, nbh0, nbh1, nbl0, nbl1);

        // ---- A-hi frags: 4 x LDS.128 ----
        uint32_t ah[4][4];
#pragma unroll
        for (int mt = 0; mt < 4; mt++) {
            uint4 v = *(const uint4*)&AsH[buf][(((wmblk * 4 + mt) * 8 + fg) * 4 + ftp) * 4];
            ah[mt][0] = v.x; ah[mt][1] = v.z; ah[mt][2] = v.y; ah[mt][3] = v.w;
        }
        // ---- B-hi frags ----
        uint32_t bh[4][2];
#pragma unroll
        for (int nt = 0; nt < 4; nt++) {
            const int c = wn + 8 * nt + fg;
            bh[nt][0] = BsH[buf][ft][c];
            bh[nt][1] = BsH[buf][ft + 4][c];
        }
        // pass 1: Ah * Bh
#pragma unroll
        for (int mt = 0; mt < 4; mt++)
#pragma unroll
            for (int nt = 0; nt < 4; nt++) mma_bf16(acc[mt][nt], ah[mt], bh[nt]);

        // ---- B-lo frags, pass 2: Ah * Bl ----
        {
            uint32_t bl[4][2];
#pragma unroll
            for (int nt = 0; nt < 4; nt++) {
                const int c = wn + 8 * nt + fg;
                bl[nt][0] = BsL[buf][ft][c];
                bl[nt][1] = BsL[buf][ft + 4][c];
            }
#pragma unroll
            for (int mt = 0; mt < 4; mt++)
#pragma unroll
                for (int nt = 0; nt < 4; nt++) mma_bf16(acc[mt][nt], ah[mt], bl[nt]);
        }

        // ---- A-lo frags, pass 3: Al * Bh ----
        {
            uint32_t al[4][4];
#pragma unroll
            for (int mt = 0; mt < 4; mt++) {
                uint4 v = *(const uint4*)&AsL[buf][(((wmblk * 4 + mt) * 8 + fg) * 4 + ftp) * 4];
                al[mt][0] = v.x; al[mt][1] = v.z; al[mt][2] = v.y; al[mt][3] = v.w;
            }
#pragma unroll
            for (int mt = 0; mt < 4; mt++)
#pragma unroll
                for (int nt = 0; nt < 4; nt++) mma_bf16(acc[mt][nt], al[mt], bh[nt]);
        }

        if (more) {
            sts_tile(buf ^ 1, na0, na1, nbh0, nbh1, nbl0, nbl1);
            __syncthreads();
            buf ^= 1;
        }
    }

    // ---------------- epilogue ----------------
#pragma unroll
    for (int nt = 0; nt < 4; nt++) {
        const int c0 = bn + wn + 8 * nt + 2 * ft;
        float b0 = 0.f, b1 = 0.f;
        if (HASBIAS) {
            b0 = __ldg(bias + c0);
            b1 = __ldg(bias + c0 + 1);
        }
#pragma unroll
        for (int mt = 0; mt < 4; mt++) {
            const int r0 = bm + wm + 16 * mt + fg;
            const int r1 = r0 + 8;
            float o00 = acc[mt][nt][0] + b0;
            float o01 = acc[mt][nt][1] + b1;
            float o10 = acc[mt][nt][2] + b0;
            float o11 = acc[mt][nt][3] + b1;
            if (CACC) {
                if (r0 < M) {
                    float id0 = 1.f / fmaxf(__ldg(deg + r0), 1.f);
                    float2 ci = *(const float2*)(Cin + (size_t)r0 * N + c0);
                    o00 += ci.x * id0;
                    o01 += ci.y * id0;
                }
                if (r1 < M) {
                    float id1 = 1.f / fmaxf(__ldg(deg + r1), 1.f);
                    float2 ci = *(const float2*)(Cin + (size_t)r1 * N + c0);
                    o10 += ci.x * id1;
                    o11 += ci.y * id1;
                }
            }
            if (RELU) {
                o00 = fmaxf(o00, 0.f); o01 = fmaxf(o01, 0.f);
                o10 = fmaxf(o10, 0.f); o11 = fmaxf(o11, 0.f);
            }
            if (r0 < M) *(float2*)(Cout + (size_t)r0 * N + c0) = make_float2(o00, o01);
            if (r1 < M) *(float2*)(Cout + (size_t)r1 * N + c0) = make_float2(o10, o11);
        }
    }
}

// ---------------- decode ----------------
__global__ void decode_kernel(const int* __restrict__ ls,
                              const int* __restrict__ ld,
                              float* __restrict__ out) {
    int gt = blockIdx.x * blockDim.x + threadIdx.x;
    int i = gt >> 5;
    int lane = gt & 31;
    if (i >= NL) return;
    int a = __ldg(ls + i);
    int b = __ldg(ld + i);
    float4 u = ((const float4*)g_z_user)[a * 32 + lane];
    float4 v = ((const float4*)g_z_item)[b * 32 + lane];
    float s = u.x * v.x + u.y * v.y + u.z * v.z + u.w * v.w;
#pragma unroll
    for (int o = 16; o > 0; o >>= 1) s += __shfl_down_sync(0xffffffffu, s, o);
    if (lane == 0) {
        out[i] = -s;
        out[NL + i] = s;
    }
}

// ---------------- host launch ----------------
extern "C" void kernel_launch(void* const* d_in, const int* in_sizes, int n_in,
                              void* d_out, int out_size) {
    const float* x_user = (const float*)d_in[0];
    const float* x_item = (const float*)d_in[1];
    const float* Wl1_ui = (const float*)d_in[2];
    const float* Wr1_ui = (const float*)d_in[3];
    const float* b1_ui  = (const float*)d_in[4];
    const float* Wl1_iu = (const float*)d_in[5];
    const float* Wr1_iu = (const float*)d_in[6];
    const float* b1_iu  = (const float*)d_in[7];
    const float* Wl2_ui = (const float*)d_in[8];
    const float* Wr2_ui = (const float*)d_in[9];
    const float* b2_ui  = (const float*)d_in[10];
    const float* Wl2_iu = (const float*)d_in[11];
    const float* Wr2_iu = (const float*)d_in[12];
    const float* b2_iu  = (const float*)d_in[13];
    const int* src_u     = (const int*)d_in[14];
    const int* dst_i     = (const int*)d_in[15];
    const int* label_src = (const int*)d_in[16];
    const int* label_dst = (const int*)d_in[17];

    float *deg_u, *deg_i, *a1i, *a1u, *hi, *hu, *c2i, *c2u, *zi, *zu;
    __nv_bfloat16 *whi, *wlo;
    cudaGetSymbolAddress((void**)&deg_u, g_deg_user);
    cudaGetSymbolAddress((void**)&deg_i, g_deg_item);
    cudaGetSymbolAddress((void**)&a1i, g_agg1_item);
    cudaGetSymbolAddress((void**)&a1u, g_agg1_user);
    cudaGetSymbolAddress((void**)&hi, g_h_item);
    cudaGetSymbolAddress((void**)&hu, g_h_user);
    cudaGetSymbolAddress((void**)&c2i, g_acc2_item);
    cudaGetSymbolAddress((void**)&c2u, g_acc2_user);
    cudaGetSymbolAddress((void**)&zi, g_z_item);
    cudaGetSymbolAddress((void**)&zu, g_z_user);
    cudaGetSymbolAddress((void**)&whi, g_whi);
    cudaGetSymbolAddress((void**)&wlo, g_wlo);

    const int MT_U = (N_USER + 127) / 128;   // 391

    // idx0: zero accumulators + degree counters
    {
        int n0 = N_ITEM * D_IN / 4, n1 = N_USER * D_IN / 4;
        int n2 = N_USER / 4, n3 = N_ITEM / 4;
        int n4 = N_ITEM * D_OUT / 4, n5 = N_USER * D_OUT / 4;
        zero_multi6<<<(n1 + 255) / 256, 256>>>((float4*)a1i, n0, (float4*)a1u, n1,
                                               (float4*)deg_u, n2, (float4*)deg_i, n3,
                                               (float4*)c2i, n4, (float4*)c2u, n5);
    }

    // idx1: weight pre-split
    wsplit_kernel<<<dim3(128, 8), 256>>>(Wl1_ui, Wr1_ui, Wl1_iu, Wr1_iu,
                                         Wl2_ui, Wr2_ui, Wl2_iu, Wr2_iu);

    // idx2: layer-1 scatter + degrees
    {
        long long threads = (long long)NE * 32;
        scatter_l1<<<(int)((threads + 255) / 256), 256>>>(x_user, x_item, src_u, dst_i);
    }

    // idx3 (profiler capture slot): layer-1 dual GEMM (user side0, item side1)
    {
        GPair P;
        P.M[0] = N_USER;            P.M[1] = N_ITEM;
        P.A1[0] = a1u;              P.A1[1] = a1i;
        P.A2[0] = x_user;           P.A2[1] = x_item;
        P.W1h[0] = whi + 2 * 32768; P.W1h[1] = whi + 0 * 32768;
        P.W1l[0] = wlo + 2 * 32768; P.W1l[1] = wlo + 0 * 32768;
        P.W2h[0] = whi + 3 * 32768; P.W2h[1] = whi + 1 * 32768;
        P.W2l[0] = wlo + 3 * 32768; P.W2l[1] = wlo + 1 * 32768;
        P.bias[0] = b1_iu;          P.bias[1] = b1_ui;
        P.deg[0] = deg_u;           P.deg[1] = deg_i;
        P.Cin[0] = nullptr;         P.Cin[1] = nullptr;
        P.C[0] = hu;                P.C[1] = hi;
        gemm_pair<128, 256, 2, true, true, false, true>
            <<<dim3(2, MT_U, 2), 256>>>(P);
    }

    // idx4: p = h @ Wl2 dual GEMM
    {
        GPair P;
        P.M[0] = N_USER;            P.M[1] = N_ITEM;
        P.A1[0] = hu;               P.A1[1] = hi;
        P.A2[0] = nullptr;          P.A2[1] = nullptr;
        P.W1h[0] = whi + 4 * 32768; P.W1h[1] = whi + 6 * 32768;
        P.W1l[0] = wlo + 4 * 32768; P.W1l[1] = wlo + 6 * 32768;
        P.W2h[0] = nullptr;         P.W2h[1] = nullptr;
        P.W2l[0] = nullptr;         P.W2l[1] = nullptr;
        P.bias[0] = nullptr;        P.bias[1] = nullptr;
        P.deg[0] = nullptr;         P.deg[1] = nullptr;
        P.Cin[0] = nullptr;         P.Cin[1] = nullptr;
        P.C[0] = a1u;               P.C[1] = a1i;
        gemm_pair<256, 128, 1, false, false, false, false>
            <<<dim3(1, MT_U, 2), 256>>>(P);
    }

    // idx5: layer-2 scatter of transformed features
    {
        long long threads = (long long)NE * 32;
        scatter_p<<<(int)((threads + 255) / 256), 256>>>(src_u, dst_i);
    }

    // idx6: z = acc2/deg + h @ Wr2 + b2 dual GEMM
    {
        GPair P;
        P.M[0] = N_USER;            P.M[1] = N_ITEM;
        P.A1[0] = hu;               P.A1[1] = hi;
        P.A2[0] = nullptr;          P.A2[1] = nullptr;
        P.W1h[0] = whi + 7 * 32768; P.W1h[1] = whi + 5 * 32768;
        P.W1l[0] = wlo + 7 * 32768; P.W1l[1] = wlo + 5 * 32768;
        P.W2h[0] = nullptr;         P.W2h[1] = nullptr;
        P.W2l[0] = nullptr;         P.W2l[1] = nullptr;
        P.bias[0] = b2_iu;          P.bias[1] = b2_ui;
        P.deg[0] = deg_u;           P.deg[1] = deg_i;
        P.Cin[0] = c2u;             P.Cin[1] = c2i;
        P.C[0] = zu;                P.C[1] = zi;
        gemm_pair<256, 128, 1, false, true, true, false>
            <<<dim3(1, MT_U, 2), 256>>>(P);
    }

    // idx7: decode
    {
        long long threads = (long long)NL * 32;
        decode_kernel<<<(int)((threads + 255) / 256), 256>>>(label_src, label_dst, (float*)d_out);
    }
}